// round 17
// baseline (speedup 1.0000x reference)
#include <cuda_runtime.h>
#include <cuda_fp16.h>
#include <math.h>
#include <stdint.h>

#define NB    4
#define NS    1024
#define NHID  1024
#define NHEADS 16
#define NKVH  4
#define DH    64
#define NE    8
#define NF    2048
#define NTOK  4096
#define QKVN  1536
#define GUN   4096

// ---------------- scratch (device globals, allocation-free) ----------------
__device__ float g_xn[NTOK * NHID];
__device__ __half g_xnh[NTOK * NHID];
__device__ __half g_atth[NTOK * NHID];
__device__ __half g_wqkvh[NHID * QKVN];
__device__ __half g_woh[NHID * NHID];
__device__ __half g_wguh[NE * NHID * GUN];   // interleaved: col 2j=gate, 2j+1=up
__device__ __half g_wdh[NE * NF * NHID];
__device__ __half g_Gh[NE * NTOK * NF];
__device__ int   g_cnt[NE];
__device__ int   g_tok[NE * NTOK];
__device__ float g_wgt[NE * NTOK];
// attention operands: Q [b][h][s][d] (scaled), Kt [b][g][d][s], V [b][g][s][d]
__device__ __half g_qh[NB * NHEADS * NS * DH];
__device__ __half g_kth[NB * NKVH * DH * NS];
__device__ __half g_vh[NB * NKVH * NS * DH];

// ---------------- helpers ----------------
__device__ __forceinline__ uint32_t pack2h(float a, float b) {
    __half2 h = __floats2half2_rn(a, b);
    return *(uint32_t*)&h;
}
__device__ __forceinline__ void ldsm4(uint32_t* r, uint32_t a) {
    asm volatile("ldmatrix.sync.aligned.m8n8.x4.shared.b16 {%0,%1,%2,%3}, [%4];\n"
        : "=r"(r[0]), "=r"(r[1]), "=r"(r[2]), "=r"(r[3]) : "r"(a));
}
__device__ __forceinline__ void ldsm4t(uint32_t* r, uint32_t a) {
    asm volatile("ldmatrix.sync.aligned.m8n8.x4.trans.shared.b16 {%0,%1,%2,%3}, [%4];\n"
        : "=r"(r[0]), "=r"(r[1]), "=r"(r[2]), "=r"(r[3]) : "r"(a));
}
__device__ __forceinline__ void mma16816(float* d, const uint32_t* a, uint32_t b0, uint32_t b1) {
    asm("mma.sync.aligned.m16n8k16.row.col.f32.f16.f16.f32 "
        "{%0,%1,%2,%3},{%4,%5,%6,%7},{%8,%9},{%0,%1,%2,%3};\n"
        : "+f"(d[0]), "+f"(d[1]), "+f"(d[2]), "+f"(d[3])
        : "r"(a[0]), "r"(a[1]), "r"(a[2]), "r"(a[3]), "r"(b0), "r"(b1));
}
__device__ __forceinline__ void cpa16(uint32_t dst, const void* src, int sz) {
    asm volatile("cp.async.cg.shared.global [%0], [%1], 16, %2;\n"
        :: "r"(dst), "l"(src), "r"(sz));
}

// ---------------- fused RMSNorm + fp16 convert ----------------
__global__ void rmsnorm_half_k(const float* __restrict__ src, const float* __restrict__ w,
                               int write_xn) {
    int t = blockIdx.x;
    const float4* xr = (const float4*)(src + (size_t)t * NHID);
    float4 v = xr[threadIdx.x];
    float ss = v.x*v.x + v.y*v.y + v.z*v.z + v.w*v.w;
    #pragma unroll
    for (int o = 16; o; o >>= 1) ss += __shfl_down_sync(0xffffffffu, ss, o);
    __shared__ float red[8];
    if ((threadIdx.x & 31) == 0) red[threadIdx.x >> 5] = ss;
    __syncthreads();
    if (threadIdx.x < 8) {
        float s = red[threadIdx.x];
        #pragma unroll
        for (int o = 4; o; o >>= 1) s += __shfl_down_sync(0xffu, s, o);
        if (threadIdx.x == 0) red[0] = s;
    }
    __syncthreads();
    float rs = rsqrtf(red[0] * (1.0f / NHID) + 1e-6f);
    float4 wv = ((const float4*)w)[threadIdx.x];
    float4 ov;
    ov.x = v.x * rs * wv.x;
    ov.y = v.y * rs * wv.y;
    ov.z = v.z * rs * wv.z;
    ov.w = v.w * rs * wv.w;
    if (write_xn) {
        ((float4*)(g_xn + (size_t)t * NHID))[threadIdx.x] = ov;
    }
    uint32_t* p = (uint32_t*)(g_xnh + (size_t)t * NHID) + threadIdx.x * 2;
    p[0] = pack2h(ov.x, ov.y);
    p[1] = pack2h(ov.z, ov.w);
}

// ---------------- combined QKV weight pack ----------------
__global__ void split_pack_qkv_k(const float4* __restrict__ Wq, const float4* __restrict__ Wk,
                                 const float4* __restrict__ Wv) {
    int i = blockIdx.x * 256 + threadIdx.x;
    int el = i * 4;
    int r = el / QKVN;
    int c = el % QKVN;
    float4 v;
    if (c < 1024)      v = Wq[(r * 1024 + c) / 4];
    else if (c < 1280) v = Wk[(r * 256 + (c - 1024)) / 4];
    else               v = Wv[(r * 256 + (c - 1280)) / 4];
    uint32_t* p = (uint32_t*)(g_wqkvh + (size_t)r * QKVN + c);
    p[0] = pack2h(v.x, v.y);
    p[1] = pack2h(v.z, v.w);
}

// ---------------- plain convert: fp32 -> fp16, 8 elems/thread ---------------
__global__ void split_k(const float4* __restrict__ ext, int n8, int sel) {
    int i = blockIdx.x * 256 + threadIdx.x;
    if (i >= n8) return;
    __half* d = (sel == 1) ? g_woh : g_wdh;
    float4 v0 = ext[i*2];
    float4 v1 = ext[i*2+1];
    uint4 o;
    o.x = pack2h(v0.x, v0.y);
    o.y = pack2h(v0.z, v0.w);
    o.z = pack2h(v1.x, v1.y);
    o.w = pack2h(v1.z, v1.w);
    *(uint4*)(d + (size_t)i * 8) = o;
}

// ---------------- gate|up interleaved pack ----------------
__global__ void split_pack_gu_k(const float4* __restrict__ Wg, const float4* __restrict__ Wu) {
    int i = blockIdx.x * 256 + threadIdx.x;
    float4 g4 = Wg[i];
    float4 u4 = Wu[i];
    int el = i * 4;
    size_t r = (size_t)(el / NF);
    int c = el % NF;
    uint4 o;
    o.x = pack2h(g4.x, u4.x);
    o.y = pack2h(g4.y, u4.y);
    o.z = pack2h(g4.z, u4.z);
    o.w = pack2h(g4.w, u4.w);
    *(uint4*)(g_wguh + r * GUN + 2 * c) = o;
}

// ---------------- tensor-core GEMM (fp16), 128x128x64 tiles, 3-stage --------
// 128 threads (4 warps of 64x64 microtiles), 2 CTA/SM, 256-reg budget
// op 0: QKV   A=g_xnh  B=g_wqkvh -> epilogue scatters fp16 Q(x0.125)/Kt/V
// op 1: Oproj A=g_atth B=g_woh   -> out (Cadd = x residual)
// op 2: GU    A=gather xnh, B=g_wguh (interleaved) -> fused silu -> g_Gh fp16
// op 3: Down  A=g_Gh   B=g_wdh   -> atomic scatter onto out
#define TG_SMEM 107520

__device__ __forceinline__ void tg_load64(
        uint32_t sA, uint32_t sB, int stg, int k0, int tid,
        const __half* apr, int asz,
        const __half* Bp, int N, int bx) {
    uint32_t abase = sA + stg * 18432 + tid * 144;
    #pragma unroll
    for (int i = 0; i < 8; i++) {
        cpa16(abase + i * 16, apr + k0 + i * 8, asz);
    }
    int brr = tid >> 1;
    int bc8 = (tid & 1) * 8;
    const __half* brow = Bp + (size_t)(k0 + brr) * N + bx;
    uint32_t bbase = sB + stg * 17408 + brr * 272;
    #pragma unroll
    for (int i = 0; i < 8; i++) {
        int c8 = bc8 + i;
        cpa16(bbase + c8 * 16, brow + c8 * 8, 16);
    }
    asm volatile("cp.async.commit_group;\n");
}

__global__ __launch_bounds__(128, 2) void tgemm_k(int op, const float* __restrict__ cadd_ext,
                                                  float* __restrict__ cout_ext) {
    extern __shared__ char smraw[];
    uint32_t sA = (uint32_t)__cvta_generic_to_shared(smraw);
    uint32_t sB = sA + 55296;

    const __half* Ah;
    const __half* Bh;
    float* C = 0;
    const float* Cadd = 0;
    int N, K, mode;
    if (op == 0) {
        Ah = g_xnh;  Bh = g_wqkvh;
        N = QKVN; K = NHID; mode = 0;
    } else if (op == 1) {
        Ah = g_atth; Bh = g_woh;
        C = cout_ext; Cadd = cadd_ext; N = NHID; K = NHID; mode = 0;
    } else if (op == 2) {
        Ah = g_xnh;  Bh = g_wguh;
        N = GUN;  K = NHID; mode = 1;
    } else {
        Ah = g_Gh;   Bh = g_wdh;
        C = cout_ext; N = NHID; K = NF; mode = 2;
    }

    int tid = threadIdx.x;
    int bx = blockIdx.x * 128;
    int by = blockIdx.y * 128;
    int e = blockIdx.z;
    int m = NTOK;
    if (mode != 0) {
        m = g_cnt[e];
        if (by >= m) return;
        Bh += (size_t)e * K * N;
    }

    // A loader: one full row per thread (row = tid), 8 x 16B chunks
    const __half* apr;
    int asz;
    {
        int lr = by + tid;
        size_t g0;
        bool v0 = true;
        if (mode == 0) {
            g0 = (size_t)lr;
        } else if (mode == 1) {
            v0 = lr < m;
            g0 = v0 ? (size_t)g_tok[e * NTOK + lr] : 0;
        } else {
            v0 = lr < m;
            g0 = (size_t)e * NTOK + (v0 ? (size_t)lr : 0);
        }
        apr = Ah + g0 * K;
        asz = v0 ? 16 : 0;
    }

    int wid = tid >> 5;
    int lane = tid & 31;
    int wm = (wid >> 1) * 64;
    int wn = (wid & 1) * 64;

    float acc[4][8][4];
    #pragma unroll
    for (int i = 0; i < 4; i++) {
        #pragma unroll
        for (int j = 0; j < 8; j++) {
            #pragma unroll
            for (int r = 0; r < 4; r++) acc[i][j][r] = 0.f;
        }
    }

    int NC = K / 64;
    tg_load64(sA, sB, 0, 0,  tid, apr, asz, Bh, N, bx);
    tg_load64(sA, sB, 1, 64, tid, apr, asz, Bh, N, bx);

    for (int c = 0; c < NC; c++) {
        if (c + 1 < NC) {
            asm volatile("cp.async.wait_group 1;\n");
        } else {
            asm volatile("cp.async.wait_group 0;\n");
        }
        __syncthreads();
        int ld = c + 2;
        if (ld < NC) {
            int ls = ld - (ld / 3) * 3;
            tg_load64(sA, sB, ls, ld * 64, tid, apr, asz, Bh, N, bx);
        }
        int st = c - (c / 3) * 3;
        uint32_t abase = sA + st * 18432;
        uint32_t bbase = sB + st * 17408;

        #pragma unroll
        for (int kk = 0; kk < 64; kk += 16) {
            uint32_t ah[4][4], bh2[4][4];
            int arow = wm + (lane & 15);
            int acolb = (kk + (lane >> 4) * 8) * 2;
            #pragma unroll
            for (int i = 0; i < 4; i++) {
                ldsm4(ah[i], abase + (arow + i*16)*144 + acolb);
            }
            int brow = kk + (lane & 15);
            #pragma unroll
            for (int ng = 0; ng < 4; ng++) {
                ldsm4t(bh2[ng], bbase + brow*272 + (wn + ng*16 + (lane >> 4)*8)*2);
            }
            #pragma unroll
            for (int i = 0; i < 4; i++) {
                #pragma unroll
                for (int n8 = 0; n8 < 8; n8++) {
                    mma16816(acc[i][n8], ah[i], bh2[n8>>1][(n8&1)*2], bh2[n8>>1][(n8&1)*2+1]);
                }
            }
        }
    }

    int ln4 = lane >> 2;
    int lc = (lane & 3) * 2;
    #pragma unroll
    for (int i = 0; i < 4; i++) {
        int r0 = wm + i * 16 + ln4;
        #pragma unroll
        for (int n8 = 0; n8 < 8; n8++) {
            int gc = bx + wn + n8 * 8 + lc;
            float* a = acc[i][n8];
            if (op == 0) {
                #pragma unroll
                for (int hh = 0; hh < 2; hh++) {
                    int row = by + r0 + hh * 8;
                    float va = a[hh*2];
                    float vb = a[hh*2+1];
                    int b = row >> 10;
                    int s = row & 1023;
                    if (gc < 1024) {
                        int h = gc >> 6, d = gc & 63;
                        size_t q = (((size_t)b * 16 + h) * 1024 + s) * 64 + d;
                        *(uint32_t*)(g_qh + q) = pack2h(va * 0.125f, vb * 0.125f);
                    } else if (gc < 1280) {
                        int cc = gc - 1024;
                        int g = cc >> 6, d = cc & 63;
                        size_t base = (((size_t)b * 4 + g) * 64 + d) * 1024 + s;
                        g_kth[base]        = __float2half(va);
                        g_kth[base + 1024] = __float2half(vb);
                    } else {
                        int cc = gc - 1280;
                        int g = cc >> 6, d = cc & 63;
                        size_t base = (((size_t)b * 4 + g) * 1024 + s) * 64 + d;
                        *(uint32_t*)(g_vh + base) = pack2h(va, vb);
                    }
                }
            } else if (mode == 0) {
                size_t o0 = (size_t)(by + r0) * N + gc;
                size_t o1 = o0 + (size_t)8 * N;
                float2 w0;
                w0.x = a[0] + Cadd[o0];
                w0.y = a[1] + Cadd[o0+1];
                float2 w1;
                w1.x = a[2] + Cadd[o1];
                w1.y = a[3] + Cadd[o1+1];
                *(float2*)(C + o0) = w0;
                *(float2*)(C + o1) = w1;
            } else if (mode == 1) {
                int s0 = by + r0;
                int s1 = s0 + 8;
                int n = gc >> 1;
                if (s0 < m) {
                    float r = a[0] / (1.f + __expf(-a[0])) * a[1];
                    g_Gh[((size_t)e * NTOK + s0) * NF + n] = __float2half(r);
                }
                if (s1 < m) {
                    float r = a[2] / (1.f + __expf(-a[2])) * a[3];
                    g_Gh[((size_t)e * NTOK + s1) * NF + n] = __float2half(r);
                }
            } else {
                int s0 = by + r0;
                int s1 = s0 + 8;
                if (s0 < m) {
                    int tk = g_tok[e*NTOK + s0];
                    float w = g_wgt[e*NTOK + s0];
                    atomicAdd(&C[(size_t)tk*N + gc],   w * a[0]);
                    atomicAdd(&C[(size_t)tk*N + gc+1], w * a[1]);
                }
                if (s1 < m) {
                    int tk = g_tok[e*NTOK + s1];
                    float w = g_wgt[e*NTOK + s1];
                    atomicAdd(&C[(size_t)tk*N + gc],   w * a[2]);
                    atomicAdd(&C[(size_t)tk*N + gc+1], w * a[3]);
                }
            }
        }
    }
}

// ---------------- mma flash attention (fp16 single) ----------------
#define FPITCH 144
#define FL_SMEM 46080

__device__ __forceinline__ void fl_load_kv(uint32_t base, int b, int g, int kv0, int tid) {
    #pragma unroll
    for (int j = 0; j < 4; j++) {
        int cc = tid + j * 128;
        int row = cc >> 3;
        int c8 = cc & 7;
        size_t koff = (((size_t)b * 4 + g) * 64 + row) * 1024 + kv0 + c8 * 8;
        cpa16(base + row * FPITCH + c8 * 16, g_kth + koff, 16);
    }
    #pragma unroll
    for (int j = 0; j < 4; j++) {
        int cc = tid + j * 128;
        int row = cc >> 3;
        int c8 = cc & 7;
        size_t voff = (((size_t)b * 4 + g) * 1024 + kv0 + row) * 64 + c8 * 8;
        cpa16(base + 9216 + row * FPITCH + c8 * 16, g_vh + voff, 16);
    }
    asm volatile("cp.async.commit_group;\n");
}

__global__ __launch_bounds__(128) void flashmma_k() {
    extern __shared__ char fsm[];
    uint32_t sb = (uint32_t)__cvta_generic_to_shared(fsm);
    int qt = blockIdx.x;
    int h = blockIdx.y;
    int b = blockIdx.z;
    int g = h >> 2;
    int tid = threadIdx.x;
    int wid = tid >> 5;
    int lane = tid & 31;

    #pragma unroll
    for (int j = 0; j < 4; j++) {
        int cc = tid + j * 128;
        int row = cc >> 3;
        int c8 = cc & 7;
        size_t qoff = (((size_t)b * 16 + h) * 1024 + qt * 64 + row) * 64 + c8 * 8;
        cpa16(sb + row * FPITCH + c8 * 16, g_qh + qoff, 16);
    }
    asm volatile("cp.async.commit_group;\n");
    fl_load_kv(sb + 9216, b, g, 0, tid);
    asm volatile("cp.async.wait_group 1;\n");
    __syncthreads();

    uint32_t ah[4][4];
    {
        int arow = wid * 16 + (lane & 15);
        #pragma unroll
        for (int j2 = 0; j2 < 4; j2++) {
            ldsm4(ah[j2], sb + arow * FPITCH + (uint32_t)(j2 * 16 + (lane >> 4) * 8) * 2);
        }
    }

    float m0 = -INFINITY, m1 = -INFINITY, l0 = 0.f, l1 = 0.f;
    float oacc[8][4];
    #pragma unroll
    for (int i = 0; i < 8; i++) {
        #pragma unroll
        for (int r = 0; r < 4; r++) oacc[i][r] = 0.f;
    }

    int r0g = qt * 64 + wid * 16 + (lane >> 2);

    for (int kt = 0; kt <= qt; kt++) {
        int st = kt & 1;
        if (kt < qt) {
            fl_load_kv(sb + 9216 + (st ^ 1) * 18432, b, g, (kt + 1) * 64, tid);
            asm volatile("cp.async.wait_group 1;\n");
        } else {
            asm volatile("cp.async.wait_group 0;\n");
        }
        __syncthreads();

        uint32_t kb = sb + 9216 + st * 18432;

        float sacc[8][4];
        #pragma unroll
        for (int i = 0; i < 8; i++) {
            #pragma unroll
            for (int r = 0; r < 4; r++) sacc[i][r] = 0.f;
        }
        #pragma unroll
        for (int j2 = 0; j2 < 4; j2++) {
            uint32_t bh2[4][4];
            int brow = j2 * 16 + (lane & 15);
            #pragma unroll
            for (int ng = 0; ng < 4; ng++) {
                ldsm4t(bh2[ng], kb + brow * FPITCH + (uint32_t)(ng * 16 + (lane >> 4) * 8) * 2);
            }
            #pragma unroll
            for (int n8 = 0; n8 < 8; n8++) {
                mma16816(sacc[n8], ah[j2], bh2[n8>>1][(n8&1)*2], bh2[n8>>1][(n8&1)*2+1]);
            }
        }

        if (kt == qt) {
            #pragma unroll
            for (int n8 = 0; n8 < 8; n8++) {
                int col = kt * 64 + n8 * 8 + (lane & 3) * 2;
                if (col > r0g)         sacc[n8][0] = -1e9f;
                if (col + 1 > r0g)     sacc[n8][1] = -1e9f;
                if (col > r0g + 8)     sacc[n8][2] = -1e9f;
                if (col + 1 > r0g + 8) sacc[n8][3] = -1e9f;
            }
        }

        float mx0 = -INFINITY, mx1 = -INFINITY;
        #pragma unroll
        for (int n8 = 0; n8 < 8; n8++) {
            mx0 = fmaxf(mx0, fmaxf(sacc[n8][0], sacc[n8][1]));
            mx1 = fmaxf(mx1, fmaxf(sacc[n8][2], sacc[n8][3]));
        }
        mx0 = fmaxf(mx0, __shfl_xor_sync(0xffffffffu, mx0, 1));
        mx0 = fmaxf(mx0, __shfl_xor_sync(0xffffffffu, mx0, 2));
        mx1 = fmaxf(mx1, __shfl_xor_sync(0xffffffffu, mx1, 1));
        mx1 = fmaxf(mx1, __shfl_xor_sync(0xffffffffu, mx1, 2));
        float nm0 = fmaxf(m0, mx0);
        float nm1 = fmaxf(m1, mx1);
        float f0 = __expf(m0 - nm0);
        float f1 = __expf(m1 - nm1);
        l0 *= f0;
        l1 *= f1;
        #pragma unroll
        for (int n8 = 0; n8 < 8; n8++) {
            oacc[n8][0] *= f0;
            oacc[n8][1] *= f0;
            oacc[n8][2] *= f1;
            oacc[n8][3] *= f1;
        }
        m0 = nm0;
        m1 = nm1;
        #pragma unroll
        for (int n8 = 0; n8 < 8; n8++) {
            float p0 = __expf(sacc[n8][0] - nm0);
            float p1 = __expf(sacc[n8][1] - nm0);
            float p2 = __expf(sacc[n8][2] - nm1);
            float p3 = __expf(sacc[n8][3] - nm1);
            l0 += p0 + p1;
            l1 += p2 + p3;
            sacc[n8][0] = p0;
            sacc[n8][1] = p1;
            sacc[n8][2] = p2;
            sacc[n8][3] = p3;
        }

        uint32_t vb = kb + 9216;
        #pragma unroll
        for (int j2 = 0; j2 < 4; j2++) {
            uint32_t pa[4];
            pa[0] = pack2h(sacc[2*j2][0],   sacc[2*j2][1]);
            pa[1] = pack2h(sacc[2*j2][2],   sacc[2*j2][3]);
            pa[2] = pack2h(sacc[2*j2+1][0], sacc[2*j2+1][1]);
            pa[3] = pack2h(sacc[2*j2+1][2], sacc[2*j2+1][3]);
            uint32_t vh2[4][4];
            int vrow = j2 * 16 + (lane & 15);
            #pragma unroll
            for (int ng = 0; ng < 4; ng++) {
                ldsm4t(vh2[ng], vb + vrow * FPITCH + (uint32_t)(ng * 16 + (lane >> 4) * 8) * 2);
            }
            #pragma unroll
            for (int n8 = 0; n8 < 8; n8++) {
                mma16816(oacc[n8], pa, vh2[n8>>1][(n8&1)*2], vh2[n8>>1][(n8&1)*2+1]);
            }
        }
        __syncthreads();
    }

    l0 += __shfl_xor_sync(0xffffffffu, l0, 1);
    l0 += __shfl_xor_sync(0xffffffffu, l0, 2);
    l1 += __shfl_xor_sync(0xffffffffu, l1, 1);
    l1 += __shfl_xor_sync(0xffffffffu, l1, 2);
    float i0 = 1.0f / l0;
    float i1 = 1.0f / l1;
    size_t t0 = (size_t)b * 1024 + r0g;
    size_t t1 = t0 + 8;
    #pragma unroll
    for (int n8 = 0; n8 < 8; n8++) {
        int col = h * 64 + n8 * 8 + (lane & 3) * 2;
        *(uint32_t*)(g_atth + t0 * NHID + col) = pack2h(oacc[n8][0] * i0, oacc[n8][1] * i0);
        *(uint32_t*)(g_atth + t1 * NHID + col) = pack2h(oacc[n8][2] * i1, oacc[n8][3] * i1);
    }
}

// ---------------- router (reads g_xn) ----------------
__global__ void router_k(const float* __restrict__ Wgate) {
    int t = blockIdx.x;
    float acc[NE];
    #pragma unroll
    for (int e = 0; e < NE; e++) acc[e] = 0.f;
    for (int h = threadIdx.x; h < NHID; h += 128) {
        float xv = g_xn[(size_t)t * NHID + h];
        const float4* wr = (const float4*)(Wgate + (size_t)h * NE);
        float4 w0 = wr[0];
        float4 w1 = wr[1];
        acc[0] += xv*w0.x; acc[1] += xv*w0.y; acc[2] += xv*w0.z; acc[3] += xv*w0.w;
        acc[4] += xv*w1.x; acc[5] += xv*w1.y; acc[6] += xv*w1.z; acc[7] += xv*w1.w;
    }
    #pragma unroll
    for (int e = 0; e < NE; e++) {
        #pragma unroll
        for (int o = 16; o; o >>= 1) acc[e] += __shfl_down_sync(0xffffffffu, acc[e], o);
    }
    __shared__ float sm[4][NE];
    int warp = threadIdx.x >> 5;
    int lane = threadIdx.x & 31;
    if (lane == 0) {
        for (int e = 0; e < NE; e++) sm[warp][e] = acc[e];
    }
    __syncthreads();
    if (threadIdx.x == 0) {
        float lg[NE];
        float mx = -INFINITY;
        for (int e = 0; e < NE; e++) {
            lg[e] = sm[0][e] + sm[1][e] + sm[2][e] + sm[3][e];
            mx = fmaxf(mx, lg[e]);
        }
        float p[NE];
        float sum = 0.f;
        for (int e = 0; e < NE; e++) { p[e] = expf(lg[e] - mx); sum += p[e]; }
        float inv = 1.0f / sum;
        for (int e = 0; e < NE; e++) p[e] *= inv;
        int i1 = 0;
        float b1 = p[0];
        for (int e = 1; e < NE; e++) {
            if (p[e] > b1) { b1 = p[e]; i1 = e; }
        }
        int i2 = -1;
        float b2 = -INFINITY;
        for (int e = 0; e < NE; e++) {
            if (e != i1 && p[e] > b2) { b2 = p[e]; i2 = e; }
        }
        int s1 = atomicAdd(&g_cnt[i1], 1);
        g_tok[i1 * NTOK + s1] = t;
        g_wgt[i1 * NTOK + s1] = b1;
        int s2 = atomicAdd(&g_cnt[i2], 1);
        g_tok[i2 * NTOK + s2] = t;
        g_wgt[i2 * NTOK + s2] = b2;
    }
}

__global__ void zero_cnt_k() {
    if (threadIdx.x < NE) g_cnt[threadIdx.x] = 0;
}

// ---------------- launch ----------------
extern "C" void kernel_launch(void* const* d_in, const int* in_sizes, int n_in,
                              void* d_out, int out_size) {
    (void)in_sizes; (void)n_in; (void)out_size;
    const float* x     = (const float*)d_in[0];
    const float* w_ln1 = (const float*)d_in[2];
    const float* w_ln2 = (const float*)d_in[3];
    const float* Wq    = (const float*)d_in[4];
    const float* Wk    = (const float*)d_in[5];
    const float* Wv    = (const float*)d_in[6];
    const float* Wo    = (const float*)d_in[7];
    const float* Wgate = (const float*)d_in[8];
    const float* Wg    = (const float*)d_in[9];
    const float* Wu    = (const float*)d_in[10];
    const float* Wd    = (const float*)d_in[11];
    float* out = (float*)d_out;

    cudaFuncSetAttribute(tgemm_k, cudaFuncAttributeMaxDynamicSharedMemorySize, TG_SMEM);
    cudaFuncSetAttribute(flashmma_k, cudaFuncAttributeMaxDynamicSharedMemorySize, FL_SMEM);

    // 0) fused QKV weight pack
    split_pack_qkv_k<<<NHID*QKVN/4/256, 256>>>((const float4*)Wq, (const float4*)Wk, (const float4*)Wv);
    // 1) Wo convert
    split_k<<<NHID*NHID/8/256, 256>>>((const float4*)Wo, NHID*NHID/8, 1);
    // 2) ln1 (fused fp16 convert)
    rmsnorm_half_k<<<NTOK, 256>>>(x, w_ln1, 0);
    // 3) fused QKV projection -> direct fp16 Q/Kt/V scatter  <-- profiled slot
    tgemm_k<<<dim3(QKVN/128, NTOK/128), 128, TG_SMEM>>>(0, 0, 0);
    // 4) mma flash attention
    flashmma_k<<<dim3(NS/64, NHEADS, NB), 128, FL_SMEM>>>();
    // 5) output proj + residual -> out (h)
    tgemm_k<<<dim3(NHID/128, NTOK/128), 128, TG_SMEM>>>(1, x, out);
    // 6) ln2 (reads h from out; fp32 copy for router)
    rmsnorm_half_k<<<NTOK, 256>>>(out, w_ln2, 1);
    // 7) routing
    zero_cnt_k<<<1, 32>>>();
    router_k<<<NTOK, 128>>>(Wgate);
    // 8) gate|up interleaved weight pack
    split_pack_gu_k<<<NE*NHID*NF/4/256, 256>>>((const float4*)Wg, (const float4*)Wu);
    // 9) fused gate|up grouped GEMM + silu epilogue -> g_Gh fp16
    tgemm_k<<<dim3(GUN/128, NTOK/128, NE), 128, TG_SMEM>>>(2, 0, 0);
    // 10) Wd convert
    split_k<<<NE*NF*NHID/8/256, 256>>>((const float4*)Wd, NE*NF*NHID/8, 3);
    // 11) down-proj scatter onto out (out already holds h from step 5)
    tgemm_k<<<dim3(NHID/128, NTOK/128, NE), 128, TG_SMEM>>>(3, 0, out);
}